// round 7
// baseline (speedup 1.0000x reference)
#include <cuda_runtime.h>
#include <math.h>
#include <stdint.h>

typedef unsigned long long u64;

// ---------------- scratch (static device globals; no allocation) -------------
__device__ float g_h1[256 * 32 * 30 * 30];   // conv1 output (relu'd)
__device__ float g_w2p[64 * 32 * 9];         // conv2 weights [c2][k][oc][par] interleaved
__device__ float g_h3[256 * 12544];          // conv2+pool output, flattened
__device__ float g_fc1[256 * 128];           // fc1 raw accumulator (pre-bias)
__device__ float g_z[256 * 48];              // backbone output
__device__ float g_dsel[256 * 48];           // class-sorted diffs (z - center[cls])
__device__ float g_cwn[10];                  // class weight / 256
__device__ int   g_seg[11];                  // class segment offsets into g_dsel

#define NPAIR 1176            // 48*49/2
#define NTRI  19600           // C(50,3)
#define NQUAD 249900          // C(51,4)
#define TRILEN 692076         // 1176*1177/2

__device__ float g_C[10 * TRILEN];           // per-class pair-pair products
__device__ int   g_qtri[NQUAD];
__device__ float g_qw[NQUAD];
__device__ float g_qt4[NQUAD];
__device__ unsigned short g_pij[NPAIR];

// ---------------- helpers ----------------------------------------------------
__device__ __forceinline__ float sgn_of(float m) { return (m < 0.f) ? -1.f : 1.f; }

__device__ __forceinline__ float sqapx(float x) {
    float y; asm("sqrt.approx.f32 %0, %1;" : "=f"(y) : "f"(x)); return y;
}
__device__ __forceinline__ float lg2apx(float x) {
    float y; asm("lg2.approx.f32 %0, %1;" : "=f"(y) : "f"(x)); return y;
}
__device__ __forceinline__ float ex2apx(float x) {
    float y; asm("ex2.approx.f32 %0, %1;" : "=f"(y) : "f"(x)); return y;
}
__device__ __forceinline__ float sr2a(float m) {
    return sgn_of(m) * (sqapx(fabsf(m) + 0.25f) - 0.5f);
}
__device__ __forceinline__ float sr3a(float m) {
    float x = fabsf(m) + 0.19245008973f;
    float r = ex2apx(lg2apx(x) * 0.3333333333f);
    return sgn_of(m) * (r - 0.57735026919f);
}
__device__ __forceinline__ float sr4a(float m) {
    return sgn_of(m) * (sqapx(sqapx(fabsf(m) + 0.15749013123f)) - 0.62996052494f);
}

__device__ __forceinline__ void decode_pair(int pi, int& i, int& j) {
    int ii = 0, rem = pi;
    while (rem >= 48 - ii) { rem -= 48 - ii; ii++; }
    i = ii; j = ii + rem;
}
__device__ __forceinline__ int pidx(int i, int j) {   // i<=j
    return i * 48 - (i * (i - 1)) / 2 + (j - i);
}

__device__ __forceinline__ float block_reduce_256(float v, float* red) {
    int tid = threadIdx.x;
    red[tid] = v; __syncthreads();
    for (int s = 128; s > 0; s >>= 1) {
        if (tid < s) red[tid] += red[tid + s];
        __syncthreads();
    }
    return red[0];
}

__device__ __forceinline__ void upk2(float& lo, float& hi, u64 v) {
    asm("mov.b64 {%0, %1}, %2;" : "=f"(lo), "=f"(hi) : "l"(v));
}
#define FMA2(d, a, b) asm("fma.rn.f32x2 %0, %1, %2, %0;" : "+l"(d) : "l"(a), "l"(b))

// ---------------- 0: init (zero + w2 interleave + quad list) -----------------
__global__ void init_k(float* __restrict__ out, const float* __restrict__ w2,
                       const float* __restrict__ mw, const float* __restrict__ gm4) {
    int e = blockIdx.x * 256 + threadIdx.x;
    if (e < 256 * 128) g_fc1[e] = 0.f;
    if (e < 4) out[2560 + e] = 0.f;
    if (e < 18432) {
        // dst [(c2*9+k)*64 + oc]*2 + par  <-  src w2[oc*288 + (2*c2+par)*9 + k]
        int par = e & 1, t = e >> 1;
        int oc = t & 63, ck = t >> 6;
        int k = ck % 9, c2 = ck / 9;
        g_w2p[e] = w2[oc * 288 + (2 * c2 + par) * 9 + k];
    }
    if (e < NPAIR) {
        int i, j; decode_pair(e, i, j);
        g_pij[e] = (unsigned short)((i << 8) | j);
    }
    if (e >= NQUAD) return;
    int r = e, a = 0, b = 0, c = 0, d;
    for (a = 0; a < 48; a++) { int n = 50 - a; int cnt = n * (n - 1) * (n - 2) / 6; if (r < cnt) break; r -= cnt; }
    for (b = a; b < 48; b++) { int n = 49 - b; int cnt = n * (n - 1) / 2; if (r < cnt) break; r -= cnt; }
    for (c = b; c < 48; c++) { int cnt = 48 - c; if (r < cnt) break; r -= cnt; }
    d = c + r;
    bool ab = (a == b), bc = (b == c), cd = (c == d);
    int perm;
    if (ab && bc && cd) perm = 1;
    else if ((ab && bc) || (bc && cd)) perm = 4;
    else if (ab && cd) perm = 6;
    else if (ab || bc || cd) perm = 12;
    else perm = 24;
    g_qw[e] = 0.25f * (float)perm * (mw[a] + mw[b] + mw[c] + mw[d]);
    int p = pidx(a, b), q = pidx(c, d);
    g_qtri[e] = p * 1176 - (p * (p - 1)) / 2 + (q - p);
    g_qt4[e] = sr4a(gm4[(((a * 48 + b) * 48) + c) * 48 + d]);
}

// ---------------- 1: conv1 (3->32, 3x3 valid, relu), sliding 3-col window ----
__global__ __launch_bounds__(256) void conv1_k(const float* __restrict__ x,
                                               const float* __restrict__ w,
                                               const float* __restrict__ bias) {
    __shared__ float xs[3 * 32 * 32];
    __shared__ float ws[32 * 27];
    __shared__ float bs[32];
    int b = blockIdx.x, tid = threadIdx.x;
    for (int i = tid; i < 3072; i += 256) xs[i] = x[b * 3072 + i];
    for (int i = tid; i < 864; i += 256) ws[i] = w[i];
    if (tid < 32) bs[tid] = bias[tid];
    __syncthreads();

    int oc = tid >> 3, ys = tid & 7;
    float wr[3][3][3];
#pragma unroll
    for (int c = 0; c < 3; c++)
#pragma unroll
        for (int ky = 0; ky < 3; ky++)
#pragma unroll
            for (int kx = 0; kx < 3; kx++)
                wr[c][ky][kx] = ws[oc * 27 + c * 9 + ky * 3 + kx];
    float bv = bs[oc];

    for (int y = ys; y < 30; y += 8) {
        float win[3][3][3];
#pragma unroll
        for (int c = 0; c < 3; c++)
#pragma unroll
            for (int ky = 0; ky < 3; ky++) {
                win[c][ky][0] = xs[c * 1024 + (y + ky) * 32 + 0];
                win[c][ky][1] = xs[c * 1024 + (y + ky) * 32 + 1];
            }
        float* orow = &g_h1[((b * 32 + oc) * 30 + y) * 30];
#pragma unroll
        for (int xc = 0; xc < 30; xc++) {
            int s2 = (xc + 2) % 3;
#pragma unroll
            for (int c = 0; c < 3; c++)
#pragma unroll
                for (int ky = 0; ky < 3; ky++)
                    win[c][ky][s2] = xs[c * 1024 + (y + ky) * 32 + xc + 2];
            float acc = bv;
#pragma unroll
            for (int c = 0; c < 3; c++)
#pragma unroll
                for (int ky = 0; ky < 3; ky++)
#pragma unroll
                    for (int kx = 0; kx < 3; kx++)
                        acc = fmaf(win[c][ky][(xc + kx) % 3], wr[c][ky][kx], acc);
            orow[xc] = fmaxf(acc, 0.f);
        }
    }
}

// ---------------- 2: conv2 + bias + relu + maxpool; c-pair f32x2 packing -----
// grid (2 oc-halves, 256 images), 224 threads = 2 prh x 14 col x 8 ocq(4 oc).
// f32x2 lanes = (even c, odd c) partial sums; BOTH operands pre-packed.
__global__ __launch_bounds__(224, 3) void conv2_k(const float* __restrict__ bias) {
    extern __shared__ float sm[];
    float* wsh = sm;                 // 16c2 x 9k x 32oc x 2par = 9216 floats (u64 per oc)
    float2* insh2 = (float2*)(sm + 9216);   // 16c2 x 6r x 30 float2 = 2880 f2
    __shared__ float bs[32];
    int oh = blockIdx.x, b = blockIdx.y, tid = threadIdx.x;

    {   // weights: dst u64 [(c2*9+k)*32 + ocl] <- src u64 [(c2*9+k)*64 + oh*32 + ocl]
        float4* wd = (float4*)wsh;
        const float4* wsrc = (const float4*)g_w2p;
        for (int i = tid; i < 2304; i += 224)
            wd[i] = wsrc[(i >> 4) * 32 + oh * 16 + (i & 15)];
        if (tid < 32) bs[tid] = bias[oh * 32 + tid];
    }

    int prh = tid / 112, rem = tid % 112, col = rem / 8, ocq = rem & 7;

    for (int it = 0; it < 7; it++) {
        __syncthreads();
        for (int i = tid; i < 2880; i += 224) {
            int c2 = i / 180, r2 = i - c2 * 180;
            int r = r2 / 30, cc = r2 - r * 30;
            const float* base = &g_h1[((b * 32 + 2 * c2) * 30 + 4 * it + r) * 30 + cc];
            float2 v; v.x = base[0]; v.y = base[900];   // c and c+1 are 30*30 apart
            insh2[i] = v;
        }
        __syncthreads();

        u64 acc2[4][4];   // [oc within quad][pool dy*2+dx]
#pragma unroll
        for (int oo = 0; oo < 4; oo++)
#pragma unroll
            for (int p = 0; p < 4; p++) acc2[oo][p] = 0ull;

        const u64* wq = (const u64*)wsh;
        for (int c2 = 0; c2 < 16; c2++) {
            const float2* ip = insh2 + c2 * 180 + prh * 60 + col * 2;
            u64 ipk[4][4];
#pragma unroll
            for (int rr = 0; rr < 4; rr++) {
                ulonglong2 va = *(const ulonglong2*)&ip[rr * 30];
                ulonglong2 vb = *(const ulonglong2*)&ip[rr * 30 + 2];
                ipk[rr][0] = va.x; ipk[rr][1] = va.y;
                ipk[rr][2] = vb.x; ipk[rr][3] = vb.y;
            }
#pragma unroll
            for (int kk = 0; kk < 9; kk++) {
                int wb = (c2 * 9 + kk) * 32 + ocq * 4;
                ulonglong2 wA = *(const ulonglong2*)&wq[wb];
                ulonglong2 wB = *(const ulonglong2*)&wq[wb + 2];
                int ky = kk / 3, kx = kk - ky * 3;
#pragma unroll
                for (int dy = 0; dy < 2; dy++)
#pragma unroll
                    for (int dx = 0; dx < 2; dx++) {
                        u64 iv = ipk[dy + ky][dx + kx];
                        FMA2(acc2[0][dy * 2 + dx], wA.x, iv);
                        FMA2(acc2[1][dy * 2 + dx], wA.y, iv);
                        FMA2(acc2[2][dy * 2 + dx], wB.x, iv);
                        FMA2(acc2[3][dy * 2 + dx], wB.y, iv);
                    }
            }
        }

        int pr = 2 * it + prh;
#pragma unroll
        for (int oo = 0; oo < 4; oo++) {
            float v[4];
#pragma unroll
            for (int p = 0; p < 4; p++) {
                float lo, hi; upk2(lo, hi, acc2[oo][p]);
                v[p] = lo + hi;   // even-c partial + odd-c partial
            }
            float m = fmaxf(fmaxf(v[0], v[1]), fmaxf(v[2], v[3]));
            int ocl = ocq * 4 + oo;
            int ocg = oh * 32 + ocl;
            g_h3[b * 12544 + ocg * 196 + pr * 14 + col] = fmaxf(m + bs[ocl], 0.f);
        }
    }
}

// ---------------- 3: fc1 GEMM split-K, BM=64 BN=128, 4x8/thread --------------
// grid (4 mtiles, 1, 56 K-splits of 224). 256 threads.
__global__ void fc1_k(const float* __restrict__ w1) {
    __shared__ __align__(16) float As[32][64];
    __shared__ __align__(16) float Ws[32][128];
    int mt = blockIdx.x, s = blockIdx.z, tid = threadIdx.x;
    int m0 = mt * 64;
    float acc[4][8];
#pragma unroll
    for (int u = 0; u < 4; u++)
#pragma unroll
        for (int v = 0; v < 8; v++) acc[u][v] = 0.f;

    int row = tid / 8, kc = (tid % 8) * 4;
    int tr = tid / 16, tc = tid % 16;

    for (int kt = 0; kt < 7; kt++) {
        int k0 = s * 224 + kt * 32;
#pragma unroll
        for (int h = 0; h < 2; h++) {
            float4 va = *(const float4*)&g_h3[(size_t)(m0 + row + 32 * h) * 12544 + k0 + kc];
            As[kc + 0][row + 32 * h] = va.x; As[kc + 1][row + 32 * h] = va.y;
            As[kc + 2][row + 32 * h] = va.z; As[kc + 3][row + 32 * h] = va.w;
        }
#pragma unroll
        for (int h = 0; h < 4; h++) {
            float4 vw = *(const float4*)&w1[(size_t)(row + 32 * h) * 12544 + k0 + kc];
            Ws[kc + 0][row + 32 * h] = vw.x; Ws[kc + 1][row + 32 * h] = vw.y;
            Ws[kc + 2][row + 32 * h] = vw.z; Ws[kc + 3][row + 32 * h] = vw.w;
        }
        __syncthreads();
#pragma unroll
        for (int kk = 0; kk < 32; kk++) {
            float4 a = *(const float4*)&As[kk][tr * 4];
            float4 w0 = *(const float4*)&Ws[kk][tc * 8];
            float4 w1v = *(const float4*)&Ws[kk][tc * 8 + 4];
            float av[4] = {a.x, a.y, a.z, a.w};
            float wv[8] = {w0.x, w0.y, w0.z, w0.w, w1v.x, w1v.y, w1v.z, w1v.w};
#pragma unroll
            for (int u = 0; u < 4; u++)
#pragma unroll
                for (int v = 0; v < 8; v++) acc[u][v] = fmaf(av[u], wv[v], acc[u][v]);
        }
        __syncthreads();
    }
#pragma unroll
    for (int u = 0; u < 4; u++)
#pragma unroll
        for (int v = 0; v < 8; v++)
            atomicAdd(&g_fc1[(m0 + tr * 4 + u) * 128 + tc * 8 + v], acc[u][v]);
}

// ---------------- 4: bias+relu, fc2 (relu), fc3 -> z; smem-staged weights ----
__global__ void fc23_k(const float* __restrict__ b1, const float* __restrict__ w2,
                       const float* __restrict__ b2, const float* __restrict__ w3,
                       const float* __restrict__ b3) {
    extern __shared__ float smw[];
    float* w2s = smw;            // [k][o] pitch 129
    float* w3s = smw + 16512;    // [k][o] pitch 48
    __shared__ float s1[128], s2[128];
    int b = blockIdx.x, tid = threadIdx.x;

    for (int i4 = tid; i4 < 4096; i4 += 128) {
        float4 v = ((const float4*)w2)[i4];
        int o = (i4 * 4) / 128, k = (i4 * 4) % 128;
        w2s[(k + 0) * 129 + o] = v.x;
        w2s[(k + 1) * 129 + o] = v.y;
        w2s[(k + 2) * 129 + o] = v.z;
        w2s[(k + 3) * 129 + o] = v.w;
    }
    for (int i4 = tid; i4 < 1536; i4 += 128) {
        float4 v = ((const float4*)w3)[i4];
        int o = (i4 * 4) / 128, k = (i4 * 4) % 128;
        w3s[(k + 0) * 48 + o] = v.x;
        w3s[(k + 1) * 48 + o] = v.y;
        w3s[(k + 2) * 48 + o] = v.z;
        w3s[(k + 3) * 48 + o] = v.w;
    }
    s1[tid] = fmaxf(g_fc1[b * 128 + tid] + b1[tid], 0.f);
    __syncthreads();

    float acc = b2[tid];
    for (int k = 0; k < 128; k++) acc = fmaf(w2s[k * 129 + tid], s1[k], acc);
    s2[tid] = fmaxf(acc, 0.f);
    __syncthreads();
    if (tid < 48) {
        float a = b3[tid];
        for (int k = 0; k < 128; k++) a = fmaf(w3s[k * 48 + tid], s2[k], a);
        g_z[b * 48 + tid] = a;
    }
}

// ---------------- 5: distances, log-softmax, argmin, class sort --------------
__global__ void prep_k(const float* __restrict__ centers, float* __restrict__ out) {
    __shared__ float cs[480];
    __shared__ int counts[10], segs[11], cursor[10];
    int tid = threadIdx.x;
    for (int i = tid; i < 480; i += 256) cs[i] = centers[i];
    if (tid < 10) { counts[tid] = 0; cursor[tid] = 0; }
    __syncthreads();

    float zr[48];
#pragma unroll
    for (int i = 0; i < 48; i++) zr[i] = g_z[tid * 48 + i];

    float dist[10];
    int best = 0; float bd = 3.4e38f;
#pragma unroll
    for (int c = 0; c < 10; c++) {
        float d = 0.f;
#pragma unroll
        for (int i = 0; i < 48; i++) {
            float t = zr[i] - cs[c * 48 + i];
            d = fmaf(t, t, d);
        }
        dist[c] = d;
        if (d < bd) { bd = d; best = c; }
    }
    float mx = -3.4e38f;
#pragma unroll
    for (int c = 0; c < 10; c++) mx = fmaxf(mx, -0.5f * dist[c]);
    float se = 0.f;
#pragma unroll
    for (int c = 0; c < 10; c++) se += expf(-0.5f * dist[c] - mx);
    float lse = logf(se);
    float lclip = logf(1e-8f);
#pragma unroll
    for (int c = 0; c < 10; c++)
        out[tid * 10 + c] = fmaxf(-0.5f * dist[c] - mx - lse, lclip);

    atomicAdd(&counts[best], 1);
    __syncthreads();
    if (tid == 0) {
        segs[0] = 0;
        for (int c = 0; c < 10; c++) segs[c + 1] = segs[c] + counts[c];
    }
    __syncthreads();
    int pos = segs[best] + atomicAdd(&cursor[best], 1);
#pragma unroll
    for (int i = 0; i < 48; i++) g_dsel[pos * 48 + i] = zr[i] - cs[best * 48 + i];
    if (tid < 10) g_cwn[tid] = (float)counts[tid] * (1.f / 256.f);
    if (tid < 11) g_seg[tid] = segs[tid];
}

// ---------------- 6: merged tail: p4a (0..1899) | p3 (1900..1976) | m12 ------
__global__ void tail_k(const float* __restrict__ mw, const float* __restrict__ gm1,
                       const float* __restrict__ gm2, const float* __restrict__ gm3,
                       float* __restrict__ out) {
    extern __shared__ float sm[];
    __shared__ unsigned short pijS[NPAIR];
    __shared__ float cwnS[10];
    __shared__ int segS[11];
    __shared__ float red[256];
    int tid = threadIdx.x;
    int bid = blockIdx.x;

    if (bid < 1900) {
        // ------- p4a: pair-product GEMM C = P^T P per class -------
        float* dsS = sm;             // up to 256*48
        float* As  = sm + 12288;     // 32*64
        float* Bs  = sm + 12288 + 2048;
        int c = bid / 190, tt = bid % 190;
        int seg0 = g_seg[c], seg1 = g_seg[c + 1];
        int rows = seg1 - seg0;
        if (rows == 0) return;
        int tp = 0;
        { int r = tt; for (tp = 0; tp < 19; tp++) { int n = 19 - tp; if (r < n) break; r -= n; } tt = r; }
        int tq = tp + tt;
        int p0 = tp * 64, q0 = tq * 64;

        for (int i = tid; i < NPAIR; i += 256) pijS[i] = g_pij[i];
        for (int i = tid; i < rows * 12; i += 256)
            ((float4*)dsS)[i] = ((const float4*)(g_dsel + seg0 * 48))[i];
        __syncthreads();

        int tr = tid >> 4, tc = tid & 15;
        float acc[4][4];
#pragma unroll
        for (int u = 0; u < 4; u++)
#pragma unroll
            for (int v = 0; v < 4; v++) acc[u][v] = 0.f;

        for (int tbase = 0; tbase < rows; tbase += 32) {
            for (int s = tid; s < 4096; s += 256) {
                int mtx = s >> 11, ss = s & 2047;
                int kkk = ss >> 6, pp = ss & 63;
                int p = (mtx ? q0 : p0) + pp;
                float v = 0.f;
                int t = tbase + kkk;
                if (p < NPAIR && t < rows) {
                    int ij = pijS[p];
                    v = dsS[t * 48 + (ij >> 8)] * dsS[t * 48 + (ij & 255)];
                }
                (mtx ? Bs : As)[ss] = v;
            }
            __syncthreads();
#pragma unroll
            for (int kkk = 0; kkk < 32; kkk++) {
                float4 a = *(const float4*)&As[kkk * 64 + tr * 4];
                float4 bv = *(const float4*)&Bs[kkk * 64 + tc * 4];
                float av[4] = {a.x, a.y, a.z, a.w};
                float bvv[4] = {bv.x, bv.y, bv.z, bv.w};
#pragma unroll
                for (int u = 0; u < 4; u++)
#pragma unroll
                    for (int v = 0; v < 4; v++) acc[u][v] = fmaf(av[u], bvv[v], acc[u][v]);
            }
            __syncthreads();
        }

        float* Cc = g_C + (size_t)c * TRILEN;
#pragma unroll
        for (int u = 0; u < 4; u++) {
            int p = p0 + tr * 4 + u;
            if (p >= NPAIR) continue;
            int rowoff = p * 1176 - (p * (p - 1)) / 2 - p;
#pragma unroll
            for (int v = 0; v < 4; v++) {
                int q = q0 + tc * 4 + v;
                if (q < NPAIR && p <= q) Cc[rowoff + q] = acc[u][v];
            }
        }
    } else if (bid < 1977) {
        // ------- p3: sorted triples -------
        float* ds = sm;   // 256*48
        for (int i = tid; i < 3072; i += 256) ((float4*)ds)[i] = ((const float4*)g_dsel)[i];
        if (tid < 10) cwnS[tid] = g_cwn[tid];
        if (tid < 11) segS[tid] = g_seg[tid];
        __syncthreads();

        int e = (bid - 1900) * 256 + tid;
        float part = 0.f;
        if (e < NTRI) {
            int r = e, a = 0, b = 0, c3;
            for (a = 0; a < 48; a++) { int n = 49 - a; int cnt = n * (n - 1) / 2; if (r < cnt) break; r -= cnt; }
            for (b = a; b < 48; b++) { int cnt = 48 - b; if (r < cnt) break; r -= cnt; }
            c3 = b + r;
            bool ab = (a == b), bc = (b == c3);
            int perm = (ab && bc) ? 1 : ((ab || bc) ? 3 : 6);
            float wgt = (float)perm * (1.f / 3.f) * (mw[a] + mw[b] + mw[c3]);
            float t3 = sr3a(gm3[((a * 48 + b) * 48) + c3]);
            for (int c = 0; c < 10; c++) {
                float acc = 0.f;
                for (int t = segS[c]; t < segS[c + 1]; t++) {
                    const float* d = ds + t * 48;
                    acc = fmaf(d[a] * d[b], d[c3], acc);
                }
                float v = sr3a(acc) - t3;
                part += cwnS[c] * wgt * v * v;
            }
        }
        float tot = block_reduce_256(part, red);
        if (tid == 0) atomicAdd(&out[2562], tot);
    } else {
        // ------- m12: p1 + p2 per class -------
        float* dss = sm;
        int c = bid - 1977;
        int s0 = g_seg[c], s1 = g_seg[c + 1];
        int rows = s1 - s0;
        float cwf = (float)rows;
        float denom = cwf + 1e-7f;
        float cwn = cwf * (1.f / 256.f);

        for (int i = tid; i < rows * 12; i += 256)
            ((float4*)dss)[i] = ((const float4*)(g_dsel + s0 * 48))[i];
        __syncthreads();

        if (tid < 48) {
            float s = 0.f;
            for (int t = 0; t < rows; t++) s += dss[t * 48 + tid];
            float m1 = s / denom;
            float d = m1 - gm1[tid];
            atomicAdd(&out[2560], cwn * mw[tid] * d * d);
        }
        float part = 0.f;
        for (int e = tid; e < 2304; e += 256) {
            int i = e / 48, j = e % 48;
            float s = 0.f;
            for (int t = 0; t < rows; t++) s = fmaf(dss[t * 48 + i], dss[t * 48 + j], s);
            float v = sr2a(s / denom) - sr2a(gm2[e]);
            part += cwn * mw[j] * v * v;
        }
        float tot = block_reduce_256(part, red);
        if (tid == 0) atomicAdd(&out[2561], tot);
    }
}

// ---------------- 7: p4 reduce over sorted quads -----------------------------
__global__ void p4b_k(float* __restrict__ out) {
    __shared__ float red[256];
    __shared__ float cw[10];
    int tid = threadIdx.x;
    if (tid < 10) cw[tid] = g_cwn[tid];
    __syncthreads();
    int e = blockIdx.x * 256 + tid;
    float part = 0.f;
    if (e < NQUAD) {
        int tri = g_qtri[e];
        float w = g_qw[e], t4 = g_qt4[e];
#pragma unroll
        for (int c = 0; c < 10; c++) {
            float cc = cw[c];
            if (cc <= 0.f) continue;
            float v = sr4a(g_C[(size_t)c * TRILEN + tri]) - t4;
            part += cc * w * v * v;
        }
    }
    float tot = block_reduce_256(part, red);
    if (tid == 0) atomicAdd(&out[2563], tot);
}

// ---------------- launch -----------------------------------------------------
extern "C" void kernel_launch(void* const* d_in, const int* in_sizes, int n_in,
                              void* d_out, int out_size) {
    const float* x    = (const float*)d_in[0];
    const float* c1w  = (const float*)d_in[1];
    const float* c1b  = (const float*)d_in[2];
    const float* c2w  = (const float*)d_in[3];
    const float* c2b  = (const float*)d_in[4];
    const float* f1w  = (const float*)d_in[5];
    const float* f1b  = (const float*)d_in[6];
    const float* f2w  = (const float*)d_in[7];
    const float* f2b  = (const float*)d_in[8];
    const float* f3w  = (const float*)d_in[9];
    const float* f3b  = (const float*)d_in[10];
    const float* cen  = (const float*)d_in[11];
    const float* mw   = (const float*)d_in[12];
    const float* gm1  = (const float*)d_in[13];
    const float* gm2  = (const float*)d_in[14];
    const float* gm3  = (const float*)d_in[15];
    const float* gm4  = (const float*)d_in[16];
    float* out = (float*)d_out;

    cudaFuncSetAttribute(conv2_k, cudaFuncAttributeMaxDynamicSharedMemorySize, 59904);
    cudaFuncSetAttribute(fc23_k, cudaFuncAttributeMaxDynamicSharedMemorySize, 90624);
    cudaFuncSetAttribute(tail_k, cudaFuncAttributeMaxDynamicSharedMemorySize, 65536);

    init_k<<<977, 256>>>(out, c2w, mw, gm4);
    conv1_k<<<256, 256>>>(x, c1w, c1b);
    conv2_k<<<dim3(2, 256), 224, 59904>>>(c2b);
    fc1_k<<<dim3(4, 1, 56), 256>>>(f1w);
    fc23_k<<<256, 128, 90624>>>(f1b, f2w, f2b, f3w, f3b);
    prep_k<<<1, 256>>>(cen, out);
    tail_k<<<1987, 256, 65536>>>(mw, gm1, gm2, gm3, out);
    p4b_k<<<977, 256>>>(out);
}

// round 8
// speedup vs baseline: 1.1356x; 1.1356x over previous
#include <cuda_runtime.h>
#include <math.h>
#include <stdint.h>

typedef unsigned long long u64;

// ---------------- scratch (static device globals; no allocation) -------------
__device__ float g_h1[256 * 32 * 30 * 30];   // conv1 output (relu'd)
__device__ float g_w2p[2 * 16 * 9 * 64];     // conv2 weights, dual-region c-pair layout
__device__ float g_h3[256 * 12544];          // conv2+pool output, flattened
__device__ float g_fc1[256 * 128];           // fc1 raw accumulator (pre-bias)
__device__ float g_z[256 * 48];              // backbone output
__device__ float g_dsel[256 * 48];           // class-sorted diffs (z - center[cls])
__device__ float g_cwn[10];                  // class weight / 256
__device__ int   g_seg[11];                  // class segment offsets into g_dsel

#define NPAIR 1176            // 48*49/2
#define NTRI  19600           // C(50,3)
#define NQUAD 249900          // C(51,4)
#define TRILEN 692076         // 1176*1177/2

__device__ float g_C[10 * TRILEN];           // per-class pair-pair products
__device__ int   g_qtri[NQUAD];
__device__ float g_qw[NQUAD];
__device__ float g_qt4[NQUAD];
__device__ unsigned short g_pij[NPAIR];

// ---------------- helpers ----------------------------------------------------
__device__ __forceinline__ float sgn_of(float m) { return (m < 0.f) ? -1.f : 1.f; }

__device__ __forceinline__ float sqapx(float x) {
    float y; asm("sqrt.approx.f32 %0, %1;" : "=f"(y) : "f"(x)); return y;
}
__device__ __forceinline__ float lg2apx(float x) {
    float y; asm("lg2.approx.f32 %0, %1;" : "=f"(y) : "f"(x)); return y;
}
__device__ __forceinline__ float ex2apx(float x) {
    float y; asm("ex2.approx.f32 %0, %1;" : "=f"(y) : "f"(x)); return y;
}
__device__ __forceinline__ float sr2a(float m) {
    return sgn_of(m) * (sqapx(fabsf(m) + 0.25f) - 0.5f);
}
__device__ __forceinline__ float sr3a(float m) {
    float x = fabsf(m) + 0.19245008973f;
    float r = ex2apx(lg2apx(x) * 0.3333333333f);
    return sgn_of(m) * (r - 0.57735026919f);
}
__device__ __forceinline__ float sr4a(float m) {
    return sgn_of(m) * (sqapx(sqapx(fabsf(m) + 0.15749013123f)) - 0.62996052494f);
}

__device__ __forceinline__ void decode_pair(int pi, int& i, int& j) {
    int ii = 0, rem = pi;
    while (rem >= 48 - ii) { rem -= 48 - ii; ii++; }
    i = ii; j = ii + rem;
}
__device__ __forceinline__ int pidx(int i, int j) {   // i<=j
    return i * 48 - (i * (i - 1)) / 2 + (j - i);
}

__device__ __forceinline__ float block_reduce_256(float v, float* red) {
    int tid = threadIdx.x;
    red[tid] = v; __syncthreads();
    for (int s = 128; s > 0; s >>= 1) {
        if (tid < s) red[tid] += red[tid + s];
        __syncthreads();
    }
    return red[0];
}

__device__ __forceinline__ void upk2(float& lo, float& hi, u64 v) {
    asm("mov.b64 {%0, %1}, %2;" : "=f"(lo), "=f"(hi) : "l"(v));
}
#define FMA2(d, a, b) asm("fma.rn.f32x2 %0, %1, %2, %0;" : "+l"(d) : "l"(a), "l"(b))

// ---------------- 0: init (zero + w2 dual-region interleave + quad list) -----
// g_w2p layout: f = oh*9216 + (c2*9+k)*64 + half*32 + q*4 + pidx*2 + par
//   oc = oh*32 + q*4 + half*2 + pidx ; source channel = 2*c2+par.
__global__ void init_k(float* __restrict__ out, const float* __restrict__ w2,
                       const float* __restrict__ mw, const float* __restrict__ gm4) {
    int e = blockIdx.x * 256 + threadIdx.x;
    if (e < 256 * 128) g_fc1[e] = 0.f;
    if (e < 4) out[2560 + e] = 0.f;
    if (e < 18432) {
        int oh = e / 9216, r = e % 9216;
        int ck = r >> 6, rem6 = r & 63;
        int half = rem6 >> 5, q = (rem6 & 31) >> 2;
        int pid2 = (rem6 >> 1) & 1, par = rem6 & 1;
        int c2 = ck / 9, k = ck % 9;
        int oc = oh * 32 + q * 4 + half * 2 + pid2;
        g_w2p[e] = w2[oc * 288 + (2 * c2 + par) * 9 + k];
    }
    if (e < NPAIR) {
        int i, j; decode_pair(e, i, j);
        g_pij[e] = (unsigned short)((i << 8) | j);
    }
    if (e >= NQUAD) return;
    int r = e, a = 0, b = 0, c = 0, d;
    for (a = 0; a < 48; a++) { int n = 50 - a; int cnt = n * (n - 1) * (n - 2) / 6; if (r < cnt) break; r -= cnt; }
    for (b = a; b < 48; b++) { int n = 49 - b; int cnt = n * (n - 1) / 2; if (r < cnt) break; r -= cnt; }
    for (c = b; c < 48; c++) { int cnt = 48 - c; if (r < cnt) break; r -= cnt; }
    d = c + r;
    bool ab = (a == b), bc = (b == c), cd = (c == d);
    int perm;
    if (ab && bc && cd) perm = 1;
    else if ((ab && bc) || (bc && cd)) perm = 4;
    else if (ab && cd) perm = 6;
    else if (ab || bc || cd) perm = 12;
    else perm = 24;
    g_qw[e] = 0.25f * (float)perm * (mw[a] + mw[b] + mw[c] + mw[d]);
    int p = pidx(a, b), q = pidx(c, d);
    g_qtri[e] = p * 1176 - (p * (p - 1)) / 2 + (q - p);
    g_qt4[e] = sr4a(gm4[(((a * 48 + b) * 48) + c) * 48 + d]);
}

// ---------------- 1: conv1 (3->32, 3x3 valid, relu), sliding 3-col window ----
__global__ __launch_bounds__(256) void conv1_k(const float* __restrict__ x,
                                               const float* __restrict__ w,
                                               const float* __restrict__ bias) {
    __shared__ float xs[3 * 32 * 32];
    __shared__ float ws[32 * 27];
    __shared__ float bs[32];
    int b = blockIdx.x, tid = threadIdx.x;
    for (int i = tid; i < 3072; i += 256) xs[i] = x[b * 3072 + i];
    for (int i = tid; i < 864; i += 256) ws[i] = w[i];
    if (tid < 32) bs[tid] = bias[tid];
    __syncthreads();

    int oc = tid >> 3, ys = tid & 7;
    float wr[3][3][3];
#pragma unroll
    for (int c = 0; c < 3; c++)
#pragma unroll
        for (int ky = 0; ky < 3; ky++)
#pragma unroll
            for (int kx = 0; kx < 3; kx++)
                wr[c][ky][kx] = ws[oc * 27 + c * 9 + ky * 3 + kx];
    float bv = bs[oc];

    for (int y = ys; y < 30; y += 8) {
        float win[3][3][3];
#pragma unroll
        for (int c = 0; c < 3; c++)
#pragma unroll
            for (int ky = 0; ky < 3; ky++) {
                win[c][ky][0] = xs[c * 1024 + (y + ky) * 32 + 0];
                win[c][ky][1] = xs[c * 1024 + (y + ky) * 32 + 1];
            }
        float* orow = &g_h1[((b * 32 + oc) * 30 + y) * 30];
#pragma unroll
        for (int xc = 0; xc < 30; xc++) {
            int s2 = (xc + 2) % 3;
#pragma unroll
            for (int c = 0; c < 3; c++)
#pragma unroll
                for (int ky = 0; ky < 3; ky++)
                    win[c][ky][s2] = xs[c * 1024 + (y + ky) * 32 + xc + 2];
            float acc = bv;
#pragma unroll
            for (int c = 0; c < 3; c++)
#pragma unroll
                for (int ky = 0; ky < 3; ky++)
#pragma unroll
                    for (int kx = 0; kx < 3; kx++)
                        acc = fmaf(win[c][ky][(xc + kx) % 3], wr[c][ky][kx], acc);
            orow[xc] = fmaxf(acc, 0.f);
        }
    }
}

// ---------------- 2: conv2 + bias + relu + maxpool; c-pair f32x2, no-conflict -
// grid (2 oc-halves, 256 images), 224 threads = 2 prh x 14 col x 8 ocq(4 oc).
// f32x2 lanes = (even c, odd c); both operands pre-packed; weight LDS.128 at
// 16B thread stride in both regions -> conflict-free.
__global__ __launch_bounds__(224, 3) void conv2_k(const float* __restrict__ bias) {
    extern __shared__ float sm[];
    float* wsh = sm;                        // 9216 floats (one oh-half)
    float2* insh2 = (float2*)(sm + 9216);   // 16c2 x 6r x 30 float2 = 2880 f2
    __shared__ float bs[32];
    int oh = blockIdx.x, b = blockIdx.y, tid = threadIdx.x;

    {   // stage this oh-half's weights (contiguous copy)
        float4* wd = (float4*)wsh;
        const float4* wsrc = (const float4*)(g_w2p) + oh * 2304;
        for (int i = tid; i < 2304; i += 224) wd[i] = wsrc[i];
        if (tid < 32) bs[tid] = bias[oh * 32 + tid];
    }

    int prh = tid / 112, rem = tid % 112, col = rem / 8, ocq = rem & 7;

    for (int it = 0; it < 7; it++) {
        __syncthreads();
        for (int i = tid; i < 2880; i += 224) {
            int c2 = i / 180, r2 = i - c2 * 180;
            int r = r2 / 30, cc = r2 - r * 30;
            const float* base = &g_h1[((b * 32 + 2 * c2) * 30 + 4 * it + r) * 30 + cc];
            float2 v; v.x = base[0]; v.y = base[900];   // c, c+1 are 900 floats apart
            insh2[i] = v;
        }
        __syncthreads();

        u64 acc2[4][4];   // [oc within quad][pool dy*2+dx]
#pragma unroll
        for (int oo = 0; oo < 4; oo++)
#pragma unroll
            for (int p = 0; p < 4; p++) acc2[oo][p] = 0ull;

        for (int c2 = 0; c2 < 16; c2++) {
            const float2* ip = insh2 + c2 * 180 + prh * 60 + col * 2;
            u64 ipk[4][4];
#pragma unroll
            for (int rr = 0; rr < 4; rr++) {
                ulonglong2 va = *(const ulonglong2*)&ip[rr * 30];
                ulonglong2 vb = *(const ulonglong2*)&ip[rr * 30 + 2];
                ipk[rr][0] = va.x; ipk[rr][1] = va.y;
                ipk[rr][2] = vb.x; ipk[rr][3] = vb.y;
            }
#pragma unroll
            for (int kk = 0; kk < 9; kk++) {
                int fb = (c2 * 9 + kk) * 64 + ocq * 4;
                ulonglong2 wA = *(const ulonglong2*)&wsh[fb];        // oc +0, +1
                ulonglong2 wB = *(const ulonglong2*)&wsh[fb + 32];   // oc +2, +3
                int ky = kk / 3, kx = kk - ky * 3;
#pragma unroll
                for (int dy = 0; dy < 2; dy++)
#pragma unroll
                    for (int dx = 0; dx < 2; dx++) {
                        u64 iv = ipk[dy + ky][dx + kx];
                        FMA2(acc2[0][dy * 2 + dx], wA.x, iv);
                        FMA2(acc2[1][dy * 2 + dx], wA.y, iv);
                        FMA2(acc2[2][dy * 2 + dx], wB.x, iv);
                        FMA2(acc2[3][dy * 2 + dx], wB.y, iv);
                    }
            }
        }

        int pr = 2 * it + prh;
#pragma unroll
        for (int oo = 0; oo < 4; oo++) {
            float v[4];
#pragma unroll
            for (int p = 0; p < 4; p++) {
                float lo, hi; upk2(lo, hi, acc2[oo][p]);
                v[p] = lo + hi;   // even-c partial + odd-c partial
            }
            float m = fmaxf(fmaxf(v[0], v[1]), fmaxf(v[2], v[3]));
            int ocl = ocq * 4 + oo;
            int ocg = oh * 32 + ocl;
            g_h3[b * 12544 + ocg * 196 + pr * 14 + col] = fmaxf(m + bs[ocl], 0.f);
        }
    }
}

// ---------------- 3: fc1 GEMM split-K (R6 config: 4x4, BN=64, 448 blocks) ----
__global__ void fc1_k(const float* __restrict__ w1) {
    __shared__ __align__(16) float As[32][64];
    __shared__ __align__(16) float Ws[32][64];
    int mt = blockIdx.x, nt = blockIdx.y, s = blockIdx.z, tid = threadIdx.x;
    int m0 = mt * 64, n0 = nt * 64;
    float acc[4][4];
#pragma unroll
    for (int u = 0; u < 4; u++)
#pragma unroll
        for (int v = 0; v < 4; v++) acc[u][v] = 0.f;

    int row = tid / 8, kc = (tid % 8) * 4;
    int tr = tid / 16, tc = tid % 16;

    for (int kt = 0; kt < 7; kt++) {
        int k0 = s * 224 + kt * 32;
#pragma unroll
        for (int h = 0; h < 2; h++) {
            float4 va = *(const float4*)&g_h3[(size_t)(m0 + row + 32 * h) * 12544 + k0 + kc];
            As[kc + 0][row + 32 * h] = va.x; As[kc + 1][row + 32 * h] = va.y;
            As[kc + 2][row + 32 * h] = va.z; As[kc + 3][row + 32 * h] = va.w;
            float4 vw = *(const float4*)&w1[(size_t)(n0 + row + 32 * h) * 12544 + k0 + kc];
            Ws[kc + 0][row + 32 * h] = vw.x; Ws[kc + 1][row + 32 * h] = vw.y;
            Ws[kc + 2][row + 32 * h] = vw.z; Ws[kc + 3][row + 32 * h] = vw.w;
        }
        __syncthreads();
#pragma unroll
        for (int kk = 0; kk < 32; kk++) {
            float4 a = *(const float4*)&As[kk][tr * 4];
            float4 wv = *(const float4*)&Ws[kk][tc * 4];
            float av[4] = {a.x, a.y, a.z, a.w};
            float wvv[4] = {wv.x, wv.y, wv.z, wv.w};
#pragma unroll
            for (int u = 0; u < 4; u++)
#pragma unroll
                for (int v = 0; v < 4; v++) acc[u][v] = fmaf(av[u], wvv[v], acc[u][v]);
        }
        __syncthreads();
    }
#pragma unroll
    for (int u = 0; u < 4; u++)
#pragma unroll
        for (int v = 0; v < 4; v++)
            atomicAdd(&g_fc1[(m0 + tr * 4 + u) * 128 + n0 + tc * 4 + v], acc[u][v]);
}

// ---------------- 4: bias+relu, fc2 (relu), fc3 -> z; smem-staged weights ----
__global__ void fc23_k(const float* __restrict__ b1, const float* __restrict__ w2,
                       const float* __restrict__ b2, const float* __restrict__ w3,
                       const float* __restrict__ b3) {
    extern __shared__ float smw[];
    float* w2s = smw;            // [k][o] pitch 129
    float* w3s = smw + 16512;    // [k][o] pitch 48
    __shared__ float s1[128], s2[128];
    int b = blockIdx.x, tid = threadIdx.x;

    for (int i4 = tid; i4 < 4096; i4 += 128) {
        float4 v = ((const float4*)w2)[i4];
        int o = (i4 * 4) / 128, k = (i4 * 4) % 128;
        w2s[(k + 0) * 129 + o] = v.x;
        w2s[(k + 1) * 129 + o] = v.y;
        w2s[(k + 2) * 129 + o] = v.z;
        w2s[(k + 3) * 129 + o] = v.w;
    }
    for (int i4 = tid; i4 < 1536; i4 += 128) {
        float4 v = ((const float4*)w3)[i4];
        int o = (i4 * 4) / 128, k = (i4 * 4) % 128;
        w3s[(k + 0) * 48 + o] = v.x;
        w3s[(k + 1) * 48 + o] = v.y;
        w3s[(k + 2) * 48 + o] = v.z;
        w3s[(k + 3) * 48 + o] = v.w;
    }
    s1[tid] = fmaxf(g_fc1[b * 128 + tid] + b1[tid], 0.f);
    __syncthreads();

    float acc = b2[tid];
    for (int k = 0; k < 128; k++) acc = fmaf(w2s[k * 129 + tid], s1[k], acc);
    s2[tid] = fmaxf(acc, 0.f);
    __syncthreads();
    if (tid < 48) {
        float a = b3[tid];
        for (int k = 0; k < 128; k++) a = fmaf(w3s[k * 48 + tid], s2[k], a);
        g_z[b * 48 + tid] = a;
    }
}

// ---------------- 5: distances, log-softmax, argmin, class sort --------------
__global__ void prep_k(const float* __restrict__ centers, float* __restrict__ out) {
    __shared__ float cs[480];
    __shared__ int counts[10], segs[11], cursor[10];
    int tid = threadIdx.x;
    for (int i = tid; i < 480; i += 256) cs[i] = centers[i];
    if (tid < 10) { counts[tid] = 0; cursor[tid] = 0; }
    __syncthreads();

    float zr[48];
#pragma unroll
    for (int i = 0; i < 48; i++) zr[i] = g_z[tid * 48 + i];

    float dist[10];
    int best = 0; float bd = 3.4e38f;
#pragma unroll
    for (int c = 0; c < 10; c++) {
        float d = 0.f;
#pragma unroll
        for (int i = 0; i < 48; i++) {
            float t = zr[i] - cs[c * 48 + i];
            d = fmaf(t, t, d);
        }
        dist[c] = d;
        if (d < bd) { bd = d; best = c; }
    }
    float mx = -3.4e38f;
#pragma unroll
    for (int c = 0; c < 10; c++) mx = fmaxf(mx, -0.5f * dist[c]);
    float se = 0.f;
#pragma unroll
    for (int c = 0; c < 10; c++) se += expf(-0.5f * dist[c] - mx);
    float lse = logf(se);
    float lclip = logf(1e-8f);
#pragma unroll
    for (int c = 0; c < 10; c++)
        out[tid * 10 + c] = fmaxf(-0.5f * dist[c] - mx - lse, lclip);

    atomicAdd(&counts[best], 1);
    __syncthreads();
    if (tid == 0) {
        segs[0] = 0;
        for (int c = 0; c < 10; c++) segs[c + 1] = segs[c] + counts[c];
    }
    __syncthreads();
    int pos = segs[best] + atomicAdd(&cursor[best], 1);
#pragma unroll
    for (int i = 0; i < 48; i++) g_dsel[pos * 48 + i] = zr[i] - cs[best * 48 + i];
    if (tid < 10) g_cwn[tid] = (float)counts[tid] * (1.f / 256.f);
    if (tid < 11) g_seg[tid] = segs[tid];
}

// ---------------- 6: p1 + p2 (per class, segment staged in smem) -------------
__global__ void m12_k(const float* __restrict__ mw, const float* __restrict__ gm1,
                      const float* __restrict__ gm2, float* __restrict__ out) {
    extern __shared__ float dss[];   // seg x 48
    __shared__ float red[256];
    int c = blockIdx.x, tid = threadIdx.x;
    int s0 = g_seg[c], s1 = g_seg[c + 1];
    int rows = s1 - s0;
    float cwf = (float)rows;
    float denom = cwf + 1e-7f;
    float cwn = cwf * (1.f / 256.f);

    for (int i = tid; i < rows * 12; i += 256)
        ((float4*)dss)[i] = ((const float4*)(g_dsel + s0 * 48))[i];
    __syncthreads();

    if (tid < 48) {
        float s = 0.f;
        for (int t = 0; t < rows; t++) s += dss[t * 48 + tid];
        float m1 = s / denom;
        float d = m1 - gm1[tid];
        atomicAdd(&out[2560], cwn * mw[tid] * d * d);
    }
    float part = 0.f;
    for (int e = tid; e < 2304; e += 256) {
        int i = e / 48, j = e % 48;
        float s = 0.f;
        for (int t = 0; t < rows; t++) s = fmaf(dss[t * 48 + i], dss[t * 48 + j], s);
        float v = sr2a(s / denom) - sr2a(gm2[e]);
        part += cwn * mw[j] * v * v;
    }
    float tot = block_reduce_256(part, red);
    if (tid == 0) atomicAdd(&out[2561], tot);
}

// ---------------- 7: p3 via sorted triples (full symmetry) -------------------
__global__ void p3_k(const float* __restrict__ mw, const float* __restrict__ gm3,
                     float* __restrict__ out) {
    extern __shared__ float ds[];   // 256*48
    __shared__ float cwnS[10];
    __shared__ int segS[11];
    __shared__ float red[256];
    int tid = threadIdx.x;
    for (int i = tid; i < 3072; i += 256) ((float4*)ds)[i] = ((const float4*)g_dsel)[i];
    if (tid < 10) cwnS[tid] = g_cwn[tid];
    if (tid < 11) segS[tid] = g_seg[tid];
    __syncthreads();

    int e = blockIdx.x * 256 + tid;
    float part = 0.f;
    if (e < NTRI) {
        int r = e, a = 0, b = 0, c3;
        for (a = 0; a < 48; a++) { int n = 49 - a; int cnt = n * (n - 1) / 2; if (r < cnt) break; r -= cnt; }
        for (b = a; b < 48; b++) { int cnt = 48 - b; if (r < cnt) break; r -= cnt; }
        c3 = b + r;
        bool ab = (a == b), bc = (b == c3);
        int perm = (ab && bc) ? 1 : ((ab || bc) ? 3 : 6);
        float wgt = (float)perm * (1.f / 3.f) * (mw[a] + mw[b] + mw[c3]);
        float t3 = sr3a(gm3[((a * 48 + b) * 48) + c3]);
        for (int c = 0; c < 10; c++) {
            float acc = 0.f;
            for (int t = segS[c]; t < segS[c + 1]; t++) {
                const float* d = ds + t * 48;
                acc = fmaf(d[a] * d[b], d[c3], acc);
            }
            float v = sr3a(acc) - t3;
            part += cwnS[c] * wgt * v * v;
        }
    }
    float tot = block_reduce_256(part, red);
    if (tid == 0) atomicAdd(&out[2562], tot);
}

// ---------------- 8a: pair-product GEMM C = P^T P per class ------------------
__global__ void p4a_k() {
    extern __shared__ float sm[];
    float* dsS = sm;             // up to 256*48
    float* As  = sm + 12288;     // 32*64
    float* Bs  = sm + 12288 + 2048;
    __shared__ unsigned short pijS[NPAIR];
    int tid = threadIdx.x;
    int c = blockIdx.y;
    int seg0 = g_seg[c], seg1 = g_seg[c + 1];
    int rows = seg1 - seg0;
    if (rows == 0) return;

    int tt = blockIdx.x, tp = 0;
    { int r = tt; for (tp = 0; tp < 19; tp++) { int n = 19 - tp; if (r < n) break; r -= n; } tt = r; }
    int tq = tp + tt;
    int p0 = tp * 64, q0 = tq * 64;

    for (int i = tid; i < NPAIR; i += 256) pijS[i] = g_pij[i];
    for (int i = tid; i < rows * 12; i += 256)
        ((float4*)dsS)[i] = ((const float4*)(g_dsel + seg0 * 48))[i];
    __syncthreads();

    int tr = tid >> 4, tc = tid & 15;
    float acc[4][4];
#pragma unroll
    for (int u = 0; u < 4; u++)
#pragma unroll
        for (int v = 0; v < 4; v++) acc[u][v] = 0.f;

    for (int tbase = 0; tbase < rows; tbase += 32) {
        for (int s = tid; s < 4096; s += 256) {
            int mtx = s >> 11, ss = s & 2047;
            int kkk = ss >> 6, pp = ss & 63;
            int p = (mtx ? q0 : p0) + pp;
            float v = 0.f;
            int t = tbase + kkk;
            if (p < NPAIR && t < rows) {
                int ij = pijS[p];
                v = dsS[t * 48 + (ij >> 8)] * dsS[t * 48 + (ij & 255)];
            }
            (mtx ? Bs : As)[ss] = v;
        }
        __syncthreads();
#pragma unroll
        for (int kkk = 0; kkk < 32; kkk++) {
            float4 a = *(const float4*)&As[kkk * 64 + tr * 4];
            float4 bv = *(const float4*)&Bs[kkk * 64 + tc * 4];
            float av[4] = {a.x, a.y, a.z, a.w};
            float bvv[4] = {bv.x, bv.y, bv.z, bv.w};
#pragma unroll
            for (int u = 0; u < 4; u++)
#pragma unroll
                for (int v = 0; v < 4; v++) acc[u][v] = fmaf(av[u], bvv[v], acc[u][v]);
        }
        __syncthreads();
    }

    float* Cc = g_C + (size_t)c * TRILEN;
#pragma unroll
    for (int u = 0; u < 4; u++) {
        int p = p0 + tr * 4 + u;
        if (p >= NPAIR) continue;
        int rowoff = p * 1176 - (p * (p - 1)) / 2 - p;
#pragma unroll
        for (int v = 0; v < 4; v++) {
            int q = q0 + tc * 4 + v;
            if (q < NPAIR && p <= q) Cc[rowoff + q] = acc[u][v];
        }
    }
}

// ---------------- 8b: p4 reduce over sorted quads ----------------------------
__global__ void p4b_k(float* __restrict__ out) {
    __shared__ float red[256];
    __shared__ float cw[10];
    int tid = threadIdx.x;
    if (tid < 10) cw[tid] = g_cwn[tid];
    __syncthreads();
    int e = blockIdx.x * 256 + tid;
    float part = 0.f;
    if (e < NQUAD) {
        int tri = g_qtri[e];
        float w = g_qw[e], t4 = g_qt4[e];
#pragma unroll
        for (int c = 0; c < 10; c++) {
            float cc = cw[c];
            if (cc <= 0.f) continue;
            float v = sr4a(g_C[(size_t)c * TRILEN + tri]) - t4;
            part += cc * w * v * v;
        }
    }
    float tot = block_reduce_256(part, red);
    if (tid == 0) atomicAdd(&out[2563], tot);
}

// ---------------- launch -----------------------------------------------------
extern "C" void kernel_launch(void* const* d_in, const int* in_sizes, int n_in,
                              void* d_out, int out_size) {
    const float* x    = (const float*)d_in[0];
    const float* c1w  = (const float*)d_in[1];
    const float* c1b  = (const float*)d_in[2];
    const float* c2w  = (const float*)d_in[3];
    const float* c2b  = (const float*)d_in[4];
    const float* f1w  = (const float*)d_in[5];
    const float* f1b  = (const float*)d_in[6];
    const float* f2w  = (const float*)d_in[7];
    const float* f2b  = (const float*)d_in[8];
    const float* f3w  = (const float*)d_in[9];
    const float* f3b  = (const float*)d_in[10];
    const float* cen  = (const float*)d_in[11];
    const float* mw   = (const float*)d_in[12];
    const float* gm1  = (const float*)d_in[13];
    const float* gm2  = (const float*)d_in[14];
    const float* gm3  = (const float*)d_in[15];
    const float* gm4  = (const float*)d_in[16];
    float* out = (float*)d_out;

    cudaFuncSetAttribute(conv2_k, cudaFuncAttributeMaxDynamicSharedMemorySize, 59904);
    cudaFuncSetAttribute(fc23_k, cudaFuncAttributeMaxDynamicSharedMemorySize, 90624);
    cudaFuncSetAttribute(p4a_k, cudaFuncAttributeMaxDynamicSharedMemorySize, 65536);
    cudaFuncSetAttribute(p3_k, cudaFuncAttributeMaxDynamicSharedMemorySize, 49152);
    cudaFuncSetAttribute(m12_k, cudaFuncAttributeMaxDynamicSharedMemorySize, 49152);

    init_k<<<977, 256>>>(out, c2w, mw, gm4);
    conv1_k<<<256, 256>>>(x, c1w, c1b);
    conv2_k<<<dim3(2, 256), 224, 59904>>>(c2b);
    fc1_k<<<dim3(4, 2, 56), 256>>>(f1w);
    fc23_k<<<256, 128, 90624>>>(f1b, f2w, f2b, f3w, f3b);
    prep_k<<<1, 256>>>(cen, out);
    m12_k<<<10, 256, 49152>>>(mw, gm1, gm2, out);
    p3_k<<<77, 256, 49152>>>(mw, gm3, out);
    p4a_k<<<dim3(190, 10), 256, 65536>>>();
    p4b_k<<<977, 256>>>(out);
}